// round 6
// baseline (speedup 1.0000x reference)
#include <cuda_runtime.h>
#include <math.h>

typedef unsigned long long ull;

#define Bsz 64
#define Tsz 512
#define Esz 256
#define Hsz 512
#define Vsz 128
#define Msz (Bsz*Tsz)   // 32768 rows

// ---------------- scratch (static device arrays; no runtime allocation) -------------
__device__ float g_xw[Msz*Hsz];     // input projection for current layer (t,b,h)
__device__ float g_hs0[Msz*Hsz];    // layer0 hidden states (t,b,h)
__device__ float g_hs1[Msz*Hsz];    // layer1 hidden states (t,b,h)

// ---------------- f32x2 helpers ------------------------------------------------------
__device__ __forceinline__ ull fma2(ull a, ull b, ull c){
    ull d; asm("fma.rn.f32x2 %0, %1, %2, %3;" : "=l"(d) : "l"(a), "l"(b), "l"(c)); return d;
}
__device__ __forceinline__ ull pack2(float x){
    ull d; asm("mov.b64 %0, {%1, %1};" : "=l"(d) : "f"(x)); return d;
}
__device__ __forceinline__ void unpack2(ull v, float& lo, float& hi){
    asm("mov.b64 {%0, %1}, %2;" : "=f"(lo), "=f"(hi) : "l"(v));
}

// branch-free tanh: 1 - 2/(e^{2x}+1). MUFU-based, ~5 instr, rel err ~3e-7.
// Saturates correctly: x->+inf => 1, x->-inf => -1.
__device__ __forceinline__ float ftanh(float x){
    float e = __expf(2.0f*x);
    return 1.0f - __fdividef(2.0f, e + 1.0f);
}

// ---------------- cluster smem helpers ----------------------------------------------
__device__ __forceinline__ unsigned smem_u32(const void* p){
    unsigned a;
    asm("{ .reg .u64 t; cvta.to.shared.u64 t, %1; cvt.u32.u64 %0, t; }" : "=r"(a) : "l"(p));
    return a;
}
__device__ __forceinline__ unsigned mapa_rank(unsigned laddr, unsigned r){
    unsigned ra; asm("mapa.shared::cluster.u32 %0, %1, %2;" : "=r"(ra) : "r"(laddr), "r"(r));
    return ra;
}
__device__ __forceinline__ void sts_remote(unsigned addr, float v){
    asm volatile("st.shared::cluster.f32 [%0], %1;" :: "r"(addr), "f"(v) : "memory");
}
__device__ __forceinline__ void cluster_arrive(){
    asm volatile("barrier.cluster.arrive.aligned;" ::: "memory");
}
__device__ __forceinline__ void cluster_wait(){
    asm volatile("barrier.cluster.wait.aligned;"   ::: "memory");
}

// ---------------- kernel: fp32 GEMM  C[M,N] = A[M,K] @ W[N,K]^T + bias --------------
// mode 0: C row-major by A-row.
// mode 1: A-row=(t*B+b) remapped to out[(b*T+t)*N+n] (logits)
// mode 2: A-row gathered through embedding: A[m][k] = emb[x[b*T+t]][k]  (K=Esz)
__global__ void __launch_bounds__(256) k_gemm(const float* __restrict__ A,
                                              const float* __restrict__ W,
                                              const float* __restrict__ bias,
                                              float* __restrict__ C,
                                              int M, int N, int K, int mode,
                                              const int* __restrict__ xidx){
    __shared__ __align__(16) float As[128*20];   // [m][k], row stride 20 (pad)
    __shared__ __align__(16) float Bs[16*130];   // [k][n], row stride 130 (pad)
    const int tid = threadIdx.x;
    const int m0 = blockIdx.x*128;
    const int n0 = blockIdx.y*128;
    const int tx = tid & 15;       // n-group (8 n each)
    const int ty = tid >> 4;       // m-group (8 m each)
    const int mlA = tid >> 2, qA = tid & 3;
    const int nnB = tid & 127, hfB = tid >> 7;

    ull acc[8][4];
#pragma unroll
    for (int i=0;i<8;i++)
#pragma unroll
        for (int j=0;j<4;j++) acc[i][j] = 0ull;

    for (int k0=0;k0<K;k0+=16){
        __syncthreads();
        // A tile: 128x16
#pragma unroll
        for (int p=0;p<2;p++){
            int m = mlA + p*64;
            int row = m0 + m;
            const float* ap;
            if (mode == 2){
                int b = row & 63; int tt = row >> 6;
                int v = xidx[b*Tsz + tt];
                ap = &A[(size_t)v*Esz + k0 + qA*4];
            } else {
                ap = &A[(size_t)row*K + k0 + qA*4];
            }
            float4 va = *(const float4*)ap;
            *(float4*)&As[m*20 + qA*4] = va;
        }
        // B tile: W[n][k] -> Bs[k][n]
        {
            const float* wp = &W[(size_t)(n0+nnB)*K + k0 + hfB*8];
            float4 v0 = *(const float4*)wp;
            float4 v1 = *(const float4*)(wp+4);
            int kb = hfB*8;
            Bs[(kb+0)*130+nnB]=v0.x; Bs[(kb+1)*130+nnB]=v0.y;
            Bs[(kb+2)*130+nnB]=v0.z; Bs[(kb+3)*130+nnB]=v0.w;
            Bs[(kb+4)*130+nnB]=v1.x; Bs[(kb+5)*130+nnB]=v1.y;
            Bs[(kb+6)*130+nnB]=v1.z; Bs[(kb+7)*130+nnB]=v1.w;
        }
        __syncthreads();
#pragma unroll
        for (int kk=0;kk<16;kk++){
            int k = (kk + tx) & 15;                 // per-lane k rotation: kills bank conflicts
            const ull* bp = (const ull*)&Bs[k*130 + tx*8];
            ull b0=bp[0], b1=bp[1], b2v=bp[2], b3=bp[3];
#pragma unroll
            for (int i=0;i<8;i++){
                ull a2 = pack2(As[(ty*8+i)*20 + k]);
                acc[i][0] = fma2(a2, b0,  acc[i][0]);
                acc[i][1] = fma2(a2, b1,  acc[i][1]);
                acc[i][2] = fma2(a2, b2v, acc[i][2]);
                acc[i][3] = fma2(a2, b3,  acc[i][3]);
            }
        }
    }
    // epilogue: + bias, write (with optional logits remap)
#pragma unroll
    for (int i=0;i<8;i++){
        int row = m0 + ty*8 + i;
        size_t obase;
        if (mode == 1){ int b = row & 63; int tt = row >> 6; obase = ((size_t)b*Tsz + tt)*(size_t)N; }
        else obase = (size_t)row * (size_t)N;
#pragma unroll
        for (int jn=0;jn<4;jn++){
            int n = n0 + tx*8 + jn*2;
            float2 bv = *(const float2*)&bias[n];
            float lo, hi; unpack2(acc[i][jn], lo, hi);
            float2 o; o.x = lo + bv.x; o.y = hi + bv.y;
            *(float2*)&C[obase + n] = o;
        }
    }
}

// ---------------- kernel: cluster-based persistent recurrence ------------------------
// 128 CTAs = 16 clusters x 8 CTAs, 512 threads/CTA (16 warps -> 4/SMSP for latency
// hiding). Cluster cl owns batches [cl*4, cl*4+4). CTA rank owns j in [rank*64, +64).
// Warp pair (wl = w&7, kh = w>>3): wl picks 8 j's, kh picks K half (256 k).
// Lane: jq = lane>>4 (j quad), kq4 = lane&15 (k slice of 16 within the half).
// Thread: jn=4 j, bn=4 batches, kn=16 k -> 64 weight floats (32 ull), 128 fma2/step.
// Intra-warp butterfly folds kq4 -> 1 partial/lane; warp pairs combine via smem red[].
// Both halves compute identical hv; kh=0 pushes to ranks 0-3, kh=1 to ranks 4-7.
#define KSL    32                  // k slices (16 floats each)
#define CHUNKF 20                  // floats per slice chunk (80B: 2-phase optimal LDS)
#define HBUF   (4*KSL*CHUNKF)      // 2560 floats per buffer

__global__ void __launch_bounds__(512,1) __cluster_dims__(8,1,1)
k_rnn(const float* __restrict__ xw, float* __restrict__ hs,
      const float* __restrict__ Whh, float* __restrict__ hlast){
    __shared__ __align__(16) float sh[2*HBUF];   // ping-pong hidden state (cluster's 4 batches)
    __shared__ __align__(16) float red[512];     // cross-warp partial sums
    const int cl   = blockIdx.x >> 3;
    const int rank = blockIdx.x & 7;
    const int tid  = threadIdx.x;
    const int w    = tid >> 5;
    const int lane = tid & 31;
    const int wl   = w & 7;
    const int kh   = w >> 3;            // k half
    const int jq   = lane >> 4;
    const int kq4  = lane & 15;
    const int j0   = rank*64 + wl*8 + jq*4;
    const int ks   = kh*16 + kq4;       // k slice 0..31
    // output after reduce+combine (same for both kh):
    const int b_out = kq4 >> 2;
    const int j_out = j0 + (kq4 & 3);
    const int bglob = cl*4 + b_out;

    // ---- weights: W_hh[j0+jj][ks*16 .. +16) as 8 f32x2 each ----
    ull w2[4][8];
#pragma unroll
    for (int jj=0;jj<4;jj++){
        const ull* wp = (const ull*)(Whh + (size_t)(j0+jj)*Hsz + ks*16);
#pragma unroll
        for (int i=0;i<8;i++) w2[jj][i] = wp[i];
    }

    // ---- DSMEM fanout addresses: this half pushes to 4 ranks ----
    const unsigned sbase = smem_u32(sh);
    unsigned ra[4];
#pragma unroll
    for (int r=0;r<4;r++) ra[r] = mapa_rank(sbase, kh*4 + r);
    // consumers read h[b][k] at ((b*KSL + (k>>4))*CHUNKF + (k&15)); our k = j_out
    const unsigned woff0 = (unsigned)(((b_out*KSL + (j_out>>4))*CHUNKF + (j_out&15))*4);
    const unsigned woff1 = woff0 + HBUF*4;

    // running pointers (stride B*H per step)
    const float* xwp = xw + (size_t)bglob*Hsz + j_out;
    float*       hsp = hs + (size_t)bglob*Hsz + j_out;

    // ---- t = 0: h_prev = 0 ----
    {
        float hv = ftanh(xwp[0]);
        if (kh == 0) hsp[0] = hv;
#pragma unroll
        for (int r=0;r<4;r++) sts_remote(ra[r] + woff0, hv);
    }
    cluster_arrive();
    float xwv = xwp[Bsz*Hsz];
    cluster_wait();
    xwp += Bsz*Hsz;
    hsp += Bsz*Hsz;

    const bool hi8 = (lane & 8) != 0;
    const bool hi4 = (lane & 4) != 0;
    const bool hi2 = (lane & 2) != 0;
    const bool hi1 = (lane & 1) != 0;

    for (int t=1;t<Tsz;t++){
        const float* bufr = sh + ((t-1)&1)*HBUF;
        ull acc[4][4];
#pragma unroll
        for (int b=0;b<4;b++)
#pragma unroll
            for (int jj=0;jj<4;jj++) acc[b][jj] = 0ull;

#pragma unroll
        for (int b=0;b<4;b++){
            const ull* hq = (const ull*)(bufr + (b*KSL + ks)*CHUNKF);
#pragma unroll
            for (int kk=0;kk<8;kk+=2){
                ulonglong2 p = *(const ulonglong2*)&hq[kk];
#pragma unroll
                for (int jj=0;jj<4;jj++){
                    acc[b][jj] = fma2(p.x, w2[jj][kk],   acc[b][jj]);
                    acc[b][jj] = fma2(p.y, w2[jj][kk+1], acc[b][jj]);
                }
            }
        }
        // collapse f32x2 -> 16 scalars v[o], o = b*4 + jj
        float v[16];
#pragma unroll
        for (int b=0;b<4;b++)
#pragma unroll
            for (int jj=0;jj<4;jj++){
                float l, h; unpack2(acc[b][jj], l, h);
                v[b*4+jj] = l + h;
            }
        // 16-lane butterfly over kq4 bits, select-based (compile-time reg indices)
#pragma unroll
        for (int o=0;o<8;o++){
            float keepv = hi8 ? v[o+8] : v[o];
            float sendv = hi8 ? v[o]   : v[o+8];
            v[o] = keepv + __shfl_xor_sync(0xffffffffu, sendv, 8);
        }
#pragma unroll
        for (int o=0;o<4;o++){
            float keepv = hi4 ? v[o+4] : v[o];
            float sendv = hi4 ? v[o]   : v[o+4];
            v[o] = keepv + __shfl_xor_sync(0xffffffffu, sendv, 4);
        }
#pragma unroll
        for (int o=0;o<2;o++){
            float keepv = hi2 ? v[o+2] : v[o];
            float sendv = hi2 ? v[o]   : v[o+2];
            v[o] = keepv + __shfl_xor_sync(0xffffffffu, sendv, 2);
        }
        {
            float keepv = hi1 ? v[1] : v[0];
            float sendv = hi1 ? v[0] : v[1];
            v[0] = keepv + __shfl_xor_sync(0xffffffffu, sendv, 1);
        }

        // cross-warp (k-half) combine via smem
        red[w*32 + lane] = v[0];
        __syncthreads();
        float sum = v[0] + red[(w^8)*32 + lane];

        float hv = ftanh(sum + xwv);
        if (kh == 0) hsp[0] = hv;

        unsigned woff = (t&1) ? woff1 : woff0;
#pragma unroll
        for (int r=0;r<4;r++) sts_remote(ra[r] + woff, hv);

        cluster_arrive();
        if (t == Tsz-1){
            if (kh == 0) hlast[(size_t)bglob*Hsz + j_out] = hv;  // inside barrier window
        } else {
            xwv = xwp[Bsz*Hsz];                                  // overlap with wait
        }
        cluster_wait();   // remote stores landed before next read / exit
        xwp += Bsz*Hsz;
        hsp += Bsz*Hsz;
    }
}

// ---------------- launch -------------------------------------------------------------
extern "C" void kernel_launch(void* const* d_in, const int* in_sizes, int n_in,
                              void* d_out, int out_size){
    const int*   x    = (const int*)  d_in[0];
    const float* emb  = (const float*)d_in[1];
    const float* Wxh0 = (const float*)d_in[2];
    const float* Whh0 = (const float*)d_in[3];
    const float* bh0  = (const float*)d_in[4];
    const float* Wxh1 = (const float*)d_in[5];
    const float* Whh1 = (const float*)d_in[6];
    const float* bh1  = (const float*)d_in[7];
    const float* Why  = (const float*)d_in[8];
    const float* by   = (const float*)d_in[9];
    float* out = (float*)d_out;

    float *xwbuf, *hs0, *hs1;
    cudaGetSymbolAddress((void**)&xwbuf, g_xw);
    cudaGetSymbolAddress((void**)&hs0,   g_hs0);
    cudaGetSymbolAddress((void**)&hs1,   g_hs1);

    const size_t LOGITS = (size_t)Bsz*Tsz*Vsz;   // 4194304

    dim3 gH(Msz/128, Hsz/128);

    // 1) xw0 = gather(emb, x) @ Wxh0^T + bh0   (gather fused into A-load)
    k_gemm<<<gH, 256>>>(emb, Wxh0, bh0, xwbuf, Msz, Hsz, Esz, 2, x);

    // 2) layer-0 recurrence -> hs0, h_last0
    k_rnn<<<128, 512>>>(xwbuf, hs0, Whh0, out + LOGITS);

    // 3) xw1 = hs0 @ Wxh1^T + bh1
    k_gemm<<<gH, 256>>>(hs0, Wxh1, bh1, xwbuf, Msz, Hsz, Hsz, 0, 0);

    // 4) layer-1 recurrence -> hs1, h_last1
    k_rnn<<<128, 512>>>(xwbuf, hs1, Whh1, out + LOGITS + (size_t)Bsz*Hsz);

    // 5) logits = hs1 @ Why^T + by  (remapped to (b,t,v))
    dim3 gV(Msz/128, Vsz/128);
    k_gemm<<<gV, 256>>>(hs1, Why, by, out, Msz, Vsz, Hsz, 1, 0);
}